// round 9
// baseline (speedup 1.0000x reference)
#include <cuda_runtime.h>
#include <stdint.h>

// ---------------- problem constants ----------------
#define BB 4
#define AA 6
#define CC 80
#define HH 128
#define WW 128
#define HWP (HH*WW)            // 16384
#define NN (AA*HWP)            // 98304
#define NCHAN (AA*(4+CC))      // 504
#define KPRE 4095
#define KPAD 4096
#define POSTK 300
#define NEGV (-(1<<30))
#define BINS 128
#define CHUNK 256
#define NCHUNK (NN/CHUNK)      // 384
#define NLAB 80
#define CAPB 1024
#define ESC (1.0f/16.0f)       // exp_shift == 4 analytically
#define OUT_ELEMS (BB*POSTK*6) // 7200

// expected input element counts (order-independent identification)
#define SZ_DATA   (BB*NCHAN*HWP)   // 33030144
#define SZ_ANCHOR (AA*4*HWP)       // 393216
#define SZ_EXPTAB 256

// ---------------- scratch (static device memory; no allocation) ----------------
__device__ int8_t  g_score[BB*NN];
__device__ uint8_t g_label[BB*NN];
__device__ int     g_hist[BB*BINS*NCHUNK];
__device__ int     g_base[BB*BINS*NCHUNK];
__device__ int     g_sortIdx[BB*KPAD];
__device__ int     g_sortScore[BB*KPAD];
__device__ int     g_sortLabel[BB*KPAD];
__device__ float4  g_boxes[BB*KPAD];
__device__ int     g_labOff[BB*(NLAB+1)];
__device__ int     g_labItems[BB*KPAD];
__device__ unsigned long long g_remv[BB*64];

// ---------------- k0: zero-fill d_out (covers poisoned padding; float dtype) ---
__global__ void k0_fill(float* __restrict__ out, int n) {
    int i = blockIdx.x * blockDim.x + threadIdx.x;
    if (i < n) out[i] = 0.0f;
}

// ---------------- k1: class max/argmax + per-chunk histogram ----------------
// bin = 127 - s for s in [1,127] (descending score), bin 127 = below-threshold.
__global__ void k1_score(const int* __restrict__ data) {
    int chunk = blockIdx.x, b = blockIdx.y, t = threadIdx.x;
    int n = chunk * CHUNK + t;
    int a = n >> 14, hw = n & (HWP - 1);
    const int* p = data + (((size_t)(b * NCHAN + a * (4 + CC) + 4)) << 14) + hw;
    int best = p[0];
    int bl = 0;
#pragma unroll 8
    for (int c = 1; c < CC; c++) {
        int v = p[(size_t)c << 14];
        if (v > best) { best = v; bl = c; }   // strict > keeps first argmax
    }
    g_score[b * NN + n] = (int8_t)best;
    g_label[b * NN + n] = (uint8_t)bl;

    __shared__ int sh[BINS];
    if (t < BINS) sh[t] = 0;
    __syncthreads();
    int bin = (best >= 1) ? (127 - best) : 127;
    atomicAdd(&sh[bin], 1);
    __syncthreads();
    if (t < BINS) g_hist[(b * BINS + t) * NCHUNK + chunk] = sh[t];
}

// ---------------- k2: global exclusive bases (bin-major, chunk-minor) ----------------
__global__ void k2_base() {
    int b = blockIdx.x, bin = threadIdx.x;
    const int* row = g_hist + (b * BINS + bin) * NCHUNK;
    int sum = 0;
    for (int c = 0; c < NCHUNK; c++) sum += row[c];
    __shared__ int tot[BINS];
    __shared__ int bb[BINS];
    tot[bin] = sum;
    __syncthreads();
    if (bin == 0) { int r = 0; for (int i = 0; i < BINS; i++) { bb[i] = r; r += tot[i]; } }
    __syncthreads();
    int run = bb[bin];
    int* orow = g_base + (b * BINS + bin) * NCHUNK;
    for (int c = 0; c < NCHUNK; c++) { int tc = row[c]; orow[c] = run; run += tc; }
}

// ---------------- k3: stable scatter, one thread per (batch, chunk) -----------
// Serial within-chunk scan => stability by construction (ascending n).
__global__ void k3_scatter() {
    int tid = blockIdx.x * blockDim.x + threadIdx.x;
    if (tid >= BB * NCHUNK) return;
    int b = tid / NCHUNK, chunk = tid % NCHUNK;
    int cnt[BINS];
#pragma unroll
    for (int i = 0; i < BINS; i++) cnt[i] = 0;
    int nb = chunk * CHUNK;
    for (int k = 0; k < CHUNK; k++) {
        int n = nb + k;
        int s = g_score[b * NN + n];
        int bin = (s >= 1) ? (127 - s) : 127;
        int pos = g_base[(b * BINS + bin) * NCHUNK + chunk] + cnt[bin];
        cnt[bin]++;
        if (pos >= 0 && pos < KPRE) {
            g_sortIdx[b * KPAD + pos] = n;
            g_sortScore[b * KPAD + pos] = (s >= 1) ? s : NEGV;
            g_sortLabel[b * KPAD + pos] = (int)g_label[b * NN + n];
        }
    }
}

// ---------------- k4: decode boxes (fp32, no-FMA) ----------------
__global__ void k4_decode(const int* __restrict__ data, const float* __restrict__ anchor,
                          const int* __restrict__ exptab) {
    int t = blockIdx.x * blockDim.x + threadIdx.x;
    int b = t >> 12, slot = t & (KPAD - 1);
    if (b >= BB || slot >= KPRE) return;
    int n = g_sortIdx[b * KPAD + slot];
    n = min(max(n, 0), NN - 1);                     // defensive clamp
    int a = n >> 14, hw = n & (HWP - 1);
    size_t db = (((size_t)(b * NCHAN + a * (4 + CC))) << 14) + hw;
    int d0 = data[db], d1 = data[db + HWP], d2 = data[db + 2 * HWP], d3 = data[db + 3 * HWP];
    size_t ab = (((size_t)(a * 4)) << 14) + hw;
    float x1 = anchor[ab], y1 = anchor[ab + HWP], x2 = anchor[ab + 2 * HWP], y2 = anchor[ab + 3 * HWP];
    float aw = __fsub_rn(x2, x1), ah = __fsub_rn(y2, y1);
    float acx = __fmul_rn(__fadd_rn(x1, x2), 0.5f);
    float acy = __fmul_rn(__fadd_rn(y1, y2), 0.5f);
    float dx = __fmul_rn((float)d0, 0.0625f);
    float dy = __fmul_rn((float)d1, 0.0625f);
    int i2 = min(max(d2, -128), 127) + 128;
    int i3 = min(max(d3, -128), 127) + 128;
    float ew = __fmul_rn((float)exptab[i2], ESC);
    float eh = __fmul_rn((float)exptab[i3], ESC);
    float pcx = __fadd_rn(acx, __fmul_rn(dx, aw));
    float pcy = __fadd_rn(acy, __fmul_rn(dy, ah));
    float pw = __fmul_rn(aw, ew), ph = __fmul_rn(ah, eh);
    float pwh = __fmul_rn(pw, 0.5f), phh = __fmul_rn(ph, 0.5f);
    float bx1 = fminf(fmaxf(__fsub_rn(pcx, pwh), 0.f), 1024.f);
    float by1 = fminf(fmaxf(__fsub_rn(pcy, phh), 0.f), 1024.f);
    float bx2 = fminf(fmaxf(__fadd_rn(pcx, pwh), 0.f), 1024.f);
    float by2 = fminf(fmaxf(__fadd_rn(pcy, phh), 0.f), 1024.f);
    g_boxes[b * KPAD + slot] = make_float4(bx1, by1, bx2, by2);
}

// ---------------- k5: remv init + stable partition by label (simple) ----------
__global__ void k5_part() {
    int b = blockIdx.x, t = threadIdx.x;   // 128 threads
    __shared__ uint8_t slab[KPAD];         // label, or 0xFF for invalid
    __shared__ int cnt[NLAB];
    __shared__ int off[NLAB + 1];
    if (t < NLAB) cnt[t] = 0;
    __syncthreads();
    for (int i = t; i < KPAD; i += 128) {
        int lab = 0xFF;
        if (i < KPRE && g_sortScore[b * KPAD + i] != NEGV) lab = g_sortLabel[b * KPAD + i];
        slab[i] = (uint8_t)lab;
        if (lab != 0xFF) atomicAdd(&cnt[lab], 1);
    }
    __syncthreads();
    if (t == 0) { int r = 0; for (int l = 0; l < NLAB; l++) { off[l] = r; r += cnt[l]; } off[NLAB] = r; }
    __syncthreads();
    if (t <= NLAB) g_labOff[b * (NLAB + 1) + t] = off[t];
    if (t < NLAB) {                        // serial stable placement per label
        int p = off[t];
        for (int i = 0; i < KPRE; i++)
            if (slab[i] == (uint8_t)t) { g_labItems[b * KPAD + p] = i; p++; }
    }
    __syncthreads();
    for (int w = t; w < 64; w += 128) {
        unsigned long long m = 0;
        for (int bit = 0; bit < 64; bit++) {
            int i = w * 64 + bit;
            if (i >= KPRE || slab[i] == 0xFF) m |= (1ull << bit);
        }
        g_remv[b * 64 + w] = m;
    }
}

// ---------------- k6: per-(batch,label) greedy NMS (exact, separable) ----------
__global__ void k6_nms() {
    int b = blockIdx.y, lab = blockIdx.x, lane = threadIdx.x;
    int s0 = g_labOff[b * (NLAB + 1) + lab];
    int s1 = g_labOff[b * (NLAB + 1) + lab + 1];
    int nl = s1 - s0;
    if (nl <= 1 || nl > KPRE) return;
    __shared__ int posArr[KPAD];
    __shared__ float4 bx[CAPB];
    __shared__ unsigned char supp[KPAD];
    for (int t = lane; t < nl; t += 32) {
        int p = g_labItems[b * KPAD + s0 + t];
        posArr[t] = p;
        if (t < CAPB) bx[t] = g_boxes[b * KPAD + p];
        supp[t] = 0;
    }
    __syncwarp();
    for (int i = 0; i < nl - 1; i++) {
        if (!supp[i]) {   // uniform branch (shared value)
            float4 bi = (i < CAPB) ? bx[i] : g_boxes[b * KPAD + posArr[i]];
            float ai = __fmul_rn(fmaxf(__fsub_rn(bi.z, bi.x), 0.f),
                                 fmaxf(__fsub_rn(bi.w, bi.y), 0.f));
            for (int j = i + 1 + lane; j < nl; j += 32) {
                if (supp[j]) continue;
                float4 bj = (j < CAPB) ? bx[j] : g_boxes[b * KPAD + posArr[j]];
                float aj = __fmul_rn(fmaxf(__fsub_rn(bj.z, bj.x), 0.f),
                                     fmaxf(__fsub_rn(bj.w, bj.y), 0.f));
                float ltx = fmaxf(bi.x, bj.x), lty = fmaxf(bi.y, bj.y);
                float rbx = fminf(bi.z, bj.z), rby = fminf(bi.w, bj.w);
                float wx = fmaxf(__fsub_rn(rbx, ltx), 0.f);
                float wy = fmaxf(__fsub_rn(rby, lty), 0.f);
                float inter = __fmul_rn(wx, wy);
                float uni = __fsub_rn(__fadd_rn(ai, aj), inter);
                float den = fmaxf(uni, 1e-6f);
                float iou = __fdiv_rn(inter, den);
                if (iou > 0.5f) supp[j] = 1;
            }
        }
        __syncwarp();
    }
    for (int t = lane; t < nl; t += 32) {
        if (supp[t]) {
            int p = posArr[t];
            atomicOr(&g_remv[b * 64 + (p >> 6)], 1ull << (p & 63));
        }
    }
}

// ---------------- k7: post-NMS top-300 + output (FLOAT dtype!) ----------------
__device__ __forceinline__ int kth_bit(unsigned long long x, int k) {
    for (int b = 0; b < 64; b++) {
        if ((x >> b) & 1ull) { if (k == 0) return b; k--; }
    }
    return 63;
}

__global__ void k7_final(float* __restrict__ out, int out_size) {
    int b = blockIdx.x, t = threadIdx.x;
    __shared__ unsigned long long kw[64], nw[64];
    __shared__ int kpre[65], npre[65];
    if (t < 64) {
        unsigned long long r = g_remv[b * 64 + t];
        kw[t] = ~r;                         // keep = valid & not suppressed
        unsigned long long nk = r;          // not-kept, minus padding bit 4095
        if (t == 63) nk &= ~(1ull << 63);
        nw[t] = nk;
    }
    __syncthreads();
    if (t == 0) {
        int rk = 0, rn = 0;
        for (int w = 0; w < 64; w++) {
            kpre[w] = rk; rk += __popcll(kw[w]);
            npre[w] = rn; rn += __popcll(nw[w]);
        }
        kpre[64] = rk; npre[64] = rn;
    }
    __syncthreads();
    if (t >= POSTK) return;
    int kc = kpre[64];
    int p, sc;
    if (t < kc) {                            // kept, in slot (score) order
        int w = 0; while (kpre[w + 1] <= t) w++;
        p = w * 64 + kth_bit(kw[w], t - kpre[w]);
        sc = g_sortScore[b * KPAD + p];
    } else {                                 // NEG fillers: not-kept, ascending slot
        int q = t - kc;
        int w = 0; while (npre[w + 1] <= q) w++;
        p = w * 64 + kth_bit(nw[w], q - npre[w]);
        sc = NEGV;
    }
    float4 bxv = g_boxes[b * KPAD + p];
    int lab = g_sortLabel[b * KPAD + p];
    int base = (b * POSTK + t) * 4;
    // write NUMERIC float values (output dtype is float32); ints here are all
    // exactly representable in fp32 (|boxes*4| <= 16384, scores in {1..127, -2^30}).
    out[base + 0] = (float)__float2int_rn(__fmul_rn(bxv.x, 4.f));  // half-even = jnp.round
    out[base + 1] = (float)__float2int_rn(__fmul_rn(bxv.y, 4.f));
    out[base + 2] = (float)__float2int_rn(__fmul_rn(bxv.z, 4.f));
    out[base + 3] = (float)__float2int_rn(__fmul_rn(bxv.w, 4.f));
    int so = BB * POSTK * 4 + b * POSTK + t;
    if (so < out_size) out[so] = (float)sc;
    int lo = BB * POSTK * 5 + b * POSTK + t;
    if (lo < out_size) out[lo] = (float)lab;
}

// ---------------- launch ----------------
extern "C" void kernel_launch(void* const* d_in, const int* in_sizes, int n_in,
                              void* d_out, int out_size) {
    // order-independent identification by element count, positional fallback
    const int*   data   = nullptr;
    const float* anchor = nullptr;
    const int*   exptab = nullptr;
    for (int i = 0; i < n_in; i++) {
        if (in_sizes[i] == SZ_DATA)        data   = (const int*)d_in[i];
        else if (in_sizes[i] == SZ_ANCHOR) anchor = (const float*)d_in[i];
        else if (in_sizes[i] == SZ_EXPTAB) exptab = (const int*)d_in[i];
    }
    if (!data   && n_in > 0) data   = (const int*)d_in[0];
    if (!anchor && n_in > 1) anchor = (const float*)d_in[1];
    if (!exptab && n_in > 2) exptab = (const int*)d_in[2];
    float* out = (float*)d_out;

    // zero-fill whole output (covers poisoned padding beyond 7200 if any)
    int fillN = out_size;
    if (fillN > 16384) fillN = 16384;
    if (fillN > 0) k0_fill<<<(fillN + 255) / 256, 256>>>(out, fillN);

    k1_score<<<dim3(NCHUNK, BB), CHUNK>>>(data);
    k2_base<<<BB, BINS>>>();
    k3_scatter<<<(BB * NCHUNK + 255) / 256, 256>>>();
    k4_decode<<<(BB * KPAD) / 256, 256>>>(data, anchor, exptab);
    k5_part<<<BB, 128>>>();
    k6_nms<<<dim3(NLAB, BB), 32>>>();
    k7_final<<<BB, 512>>>(out, out_size);
}

// round 11
// speedup vs baseline: 1.6379x; 1.6379x over previous
#include <cuda_runtime.h>
#include <stdint.h>

// ---------------- problem constants ----------------
#define BB 4
#define AA 6
#define CC 80
#define HH 128
#define WW 128
#define HWP (HH*WW)            // 16384
#define NN (AA*HWP)            // 98304
#define NCHAN (AA*(4+CC))      // 504
#define KPRE 4095
#define KPAD 4096
#define POSTK 300
#define NEGV (-(1<<30))
#define BINS 128
#define CHUNK 1024
#define NCHUNK (NN/CHUNK)      // 96
#define NLAB 80
#define CAPB 1024
#define ESC (1.0f/16.0f)       // exp_shift == 4 analytically
#define OUT_ELEMS (BB*POSTK*6) // 7200

// expected input element counts (order-independent identification)
#define SZ_DATA   (BB*NCHAN*HWP)   // 33030144
#define SZ_ANCHOR (AA*4*HWP)       // 393216
#define SZ_EXPTAB 256

// ---------------- scratch (static device memory; no allocation) ----------------
__device__ int8_t  g_score[BB*NN];
__device__ uint8_t g_label[BB*NN];
__device__ int     g_hist[BB*BINS*NCHUNK];
__device__ int     g_base[BB*BINS*NCHUNK];
__device__ int     g_sortIdx[BB*KPAD];
__device__ int     g_sortScore[BB*KPAD];
__device__ int     g_sortLabel[BB*KPAD];
__device__ float4  g_boxes[BB*KPAD];
__device__ int     g_labOff[BB*(NLAB+1)];
__device__ int     g_labItems[BB*KPAD];
__device__ unsigned long long g_remv[BB*64];

// ---------------- k0: zero-fill d_out ----------------
__global__ void k0_fill(float* __restrict__ out, int n) {
    int i = blockIdx.x * blockDim.x + threadIdx.x;
    if (i < n) out[i] = 0.0f;
}

// ---------------- k1: class max/argmax (int4-vectorized) + per-chunk histogram -
// Each thread owns 4 consecutive hw positions; block covers a 1024-chunk.
// bin = 127 - s for s in [1,127] (descending score), bin 127 = below-threshold.
__global__ void k1_score(const int* __restrict__ data) {
    int chunk = blockIdx.x, b = blockIdx.y, t = threadIdx.x;
    int n0 = chunk * CHUNK + t * 4;
    int a = n0 >> 14, hw = n0 & (HWP - 1);     // all 4 lanes share the same anchor a
    const int* p = data + (((size_t)(b * NCHAN + a * (4 + CC) + 4)) << 14) + hw;
    int4 v = *(const int4*)p;
    int b0 = v.x, b1 = v.y, b2 = v.z, b3 = v.w;
    int l0 = 0, l1 = 0, l2 = 0, l3 = 0;
#pragma unroll 8
    for (int c = 1; c < CC; c++) {
        int4 w = *(const int4*)(p + ((size_t)c << 14));
        if (w.x > b0) { b0 = w.x; l0 = c; }
        if (w.y > b1) { b1 = w.y; l1 = c; }
        if (w.z > b2) { b2 = w.z; l2 = c; }
        if (w.w > b3) { b3 = w.w; l3 = c; }
    }
    char4 sc4; sc4.x = (char)b0; sc4.y = (char)b1; sc4.z = (char)b2; sc4.w = (char)b3;
    *(char4*)&g_score[b * NN + n0] = sc4;
    uchar4 lb4; lb4.x = (unsigned char)l0; lb4.y = (unsigned char)l1;
    lb4.z = (unsigned char)l2; lb4.w = (unsigned char)l3;
    *(uchar4*)&g_label[b * NN + n0] = lb4;

    __shared__ int sh[BINS];
    if (t < BINS) sh[t] = 0;
    __syncthreads();
    atomicAdd(&sh[(b0 >= 1) ? (127 - b0) : 127], 1);
    atomicAdd(&sh[(b1 >= 1) ? (127 - b1) : 127], 1);
    atomicAdd(&sh[(b2 >= 1) ? (127 - b2) : 127], 1);
    atomicAdd(&sh[(b3 >= 1) ? (127 - b3) : 127], 1);
    __syncthreads();
    if (t < BINS) g_hist[(b * BINS + t) * NCHUNK + chunk] = sh[t];
}

// ---------------- k2: global exclusive bases (bin-major, chunk-minor) ----------
__global__ void k2_base() {
    int b = blockIdx.x, bin = threadIdx.x;
    const int* row = g_hist + (b * BINS + bin) * NCHUNK;
    int sum = 0;
#pragma unroll 8
    for (int c = 0; c < NCHUNK; c++) sum += row[c];
    __shared__ int tot[BINS];
    __shared__ int bb[BINS];
    tot[bin] = sum;
    __syncthreads();
    if (bin == 0) { int r = 0; for (int i = 0; i < BINS; i++) { bb[i] = r; r += tot[i]; } }
    __syncthreads();
    int run = bb[bin];
    int* orow = g_base + (b * BINS + bin) * NCHUNK;
#pragma unroll 8
    for (int c = 0; c < NCHUNK; c++) { int tc = row[c]; orow[c] = run; run += tc; }
}

// ---------------- k3: warp-parallel stable scatter of the top-KPRE -------------
// One warp per 1024-chunk; groups ascending + lanes ascending => stable.
__global__ void k3_scatter() {
    int b = blockIdx.y;
    int wid = threadIdx.x >> 5, lane = threadIdx.x & 31;
    int chunk = blockIdx.x * 4 + wid;
    __shared__ int cnt[4][BINS];
    for (int i = lane; i < BINS; i += 32) cnt[wid][i] = 0;
    __syncwarp();
    for (int g = 0; g < CHUNK / 32; g++) {
        int n = chunk * CHUNK + g * 32 + lane;
        int s = g_score[b * NN + n];
        int lab = g_label[b * NN + n];
        int bin = (s >= 1) ? (127 - s) : 127;
        unsigned m = __match_any_sync(0xffffffffu, bin);
        int prior = cnt[wid][bin];
        __syncwarp();
        if (lane == __ffs(m) - 1) cnt[wid][bin] = prior + __popc(m);
        __syncwarp();
        int ltr = __popc(m & ((1u << lane) - 1u));
        int pos = g_base[(b * BINS + bin) * NCHUNK + chunk] + prior + ltr;
        if (pos < KPRE) {
            g_sortIdx[b * KPAD + pos] = n;
            g_sortScore[b * KPAD + pos] = (s >= 1) ? s : NEGV;
            g_sortLabel[b * KPAD + pos] = lab;
        }
    }
}

// ---------------- k4: decode boxes (fp32, no-FMA) ----------------
__global__ void k4_decode(const int* __restrict__ data, const float* __restrict__ anchor,
                          const int* __restrict__ exptab) {
    int t = blockIdx.x * blockDim.x + threadIdx.x;
    int b = t >> 12, slot = t & (KPAD - 1);
    if (b >= BB || slot >= KPRE) return;
    int n = g_sortIdx[b * KPAD + slot];
    n = min(max(n, 0), NN - 1);
    int a = n >> 14, hw = n & (HWP - 1);
    size_t db = (((size_t)(b * NCHAN + a * (4 + CC))) << 14) + hw;
    int d0 = data[db], d1 = data[db + HWP], d2 = data[db + 2 * HWP], d3 = data[db + 3 * HWP];
    size_t ab = (((size_t)(a * 4)) << 14) + hw;
    float x1 = anchor[ab], y1 = anchor[ab + HWP], x2 = anchor[ab + 2 * HWP], y2 = anchor[ab + 3 * HWP];
    float aw = __fsub_rn(x2, x1), ah = __fsub_rn(y2, y1);
    float acx = __fmul_rn(__fadd_rn(x1, x2), 0.5f);
    float acy = __fmul_rn(__fadd_rn(y1, y2), 0.5f);
    float dx = __fmul_rn((float)d0, 0.0625f);
    float dy = __fmul_rn((float)d1, 0.0625f);
    int i2 = min(max(d2, -128), 127) + 128;
    int i3 = min(max(d3, -128), 127) + 128;
    float ew = __fmul_rn((float)exptab[i2], ESC);
    float eh = __fmul_rn((float)exptab[i3], ESC);
    float pcx = __fadd_rn(acx, __fmul_rn(dx, aw));
    float pcy = __fadd_rn(acy, __fmul_rn(dy, ah));
    float pw = __fmul_rn(aw, ew), ph = __fmul_rn(ah, eh);
    float pwh = __fmul_rn(pw, 0.5f), phh = __fmul_rn(ph, 0.5f);
    float bx1 = fminf(fmaxf(__fsub_rn(pcx, pwh), 0.f), 1024.f);
    float by1 = fminf(fmaxf(__fsub_rn(pcy, phh), 0.f), 1024.f);
    float bx2 = fminf(fmaxf(__fadd_rn(pcx, pwh), 0.f), 1024.f);
    float by2 = fminf(fmaxf(__fadd_rn(pcy, phh), 0.f), 1024.f);
    g_boxes[b * KPAD + slot] = make_float4(bx1, by1, bx2, by2);
}

// ---------------- k5: remv init (ballot) + warp-parallel stable partition ------
__global__ void k5_part() {
    int b = blockIdx.x, lane = threadIdx.x;   // one warp per batch
    // removed = invalid (NEG) or padding slot 4095; build via ballots
    for (int w = 0; w < 64; w++) {
        int i0 = w * 64 + lane, i1 = w * 64 + 32 + lane;
        unsigned lo = __ballot_sync(0xffffffffu,
            (i0 >= KPRE) || (g_sortScore[b * KPAD + i0] == NEGV));
        unsigned hi = __ballot_sync(0xffffffffu,
            (i1 >= KPRE) || (g_sortScore[b * KPAD + i1] == NEGV));
        if (lane == 0)
            g_remv[b * 64 + w] = (unsigned long long)lo | ((unsigned long long)hi << 32);
    }
    __shared__ int cnt[NLAB + 1];
    __shared__ int off[NLAB + 1];
    __shared__ int run[NLAB + 1];
    for (int i = lane; i < NLAB + 1; i += 32) cnt[i] = 0;
    __syncwarp();
    for (int g = 0; g < KPAD / 32; g++) {
        int idx = g * 32 + lane;
        int bin = NLAB;
        if (idx < KPRE && g_sortScore[b * KPAD + idx] != NEGV) bin = g_sortLabel[b * KPAD + idx];
        unsigned m = __match_any_sync(0xffffffffu, bin);
        if (lane == __ffs(m) - 1) atomicAdd(&cnt[bin], __popc(m));
    }
    __syncwarp();
    if (lane == 0) { int r = 0; for (int i = 0; i < NLAB; i++) { off[i] = r; r += cnt[i]; } off[NLAB] = r; }
    __syncwarp();
    for (int i = lane; i < NLAB + 1; i += 32) { g_labOff[b * (NLAB + 1) + i] = off[i]; run[i] = off[i]; }
    __syncwarp();
    for (int g = 0; g < KPAD / 32; g++) {
        int idx = g * 32 + lane;
        int bin = NLAB;
        if (idx < KPRE && g_sortScore[b * KPAD + idx] != NEGV) bin = g_sortLabel[b * KPAD + idx];
        unsigned m = __match_any_sync(0xffffffffu, bin);
        int prior = run[bin];
        __syncwarp();
        if (lane == __ffs(m) - 1) run[bin] = prior + __popc(m);
        __syncwarp();
        if (bin < NLAB) {
            int p = prior + __popc(m & ((1u << lane) - 1u));
            g_labItems[b * KPAD + p] = idx;
        }
    }
}

// ---------------- k6: per-(batch,label) greedy NMS (exact, separable) ----------
__global__ void k6_nms() {
    int b = blockIdx.y, lab = blockIdx.x, lane = threadIdx.x;
    int s0 = g_labOff[b * (NLAB + 1) + lab];
    int s1 = g_labOff[b * (NLAB + 1) + lab + 1];
    int nl = s1 - s0;
    if (nl <= 1 || nl > KPRE) return;
    __shared__ int posArr[KPAD];
    __shared__ float4 bx[CAPB];
    __shared__ unsigned char supp[KPAD];
    for (int t = lane; t < nl; t += 32) {
        int p = g_labItems[b * KPAD + s0 + t];
        posArr[t] = p;
        if (t < CAPB) bx[t] = g_boxes[b * KPAD + p];
        supp[t] = 0;
    }
    __syncwarp();
    for (int i = 0; i < nl - 1; i++) {
        if (!supp[i]) {   // uniform branch (shared value)
            float4 bi = (i < CAPB) ? bx[i] : g_boxes[b * KPAD + posArr[i]];
            float ai = __fmul_rn(fmaxf(__fsub_rn(bi.z, bi.x), 0.f),
                                 fmaxf(__fsub_rn(bi.w, bi.y), 0.f));
            for (int j = i + 1 + lane; j < nl; j += 32) {
                if (supp[j]) continue;
                float4 bj = (j < CAPB) ? bx[j] : g_boxes[b * KPAD + posArr[j]];
                float aj = __fmul_rn(fmaxf(__fsub_rn(bj.z, bj.x), 0.f),
                                     fmaxf(__fsub_rn(bj.w, bj.y), 0.f));
                float ltx = fmaxf(bi.x, bj.x), lty = fmaxf(bi.y, bj.y);
                float rbx = fminf(bi.z, bj.z), rby = fminf(bi.w, bj.w);
                float wx = fmaxf(__fsub_rn(rbx, ltx), 0.f);
                float wy = fmaxf(__fsub_rn(rby, lty), 0.f);
                float inter = __fmul_rn(wx, wy);
                float uni = __fsub_rn(__fadd_rn(ai, aj), inter);
                float den = fmaxf(uni, 1e-6f);
                float iou = __fdiv_rn(inter, den);
                if (iou > 0.5f) supp[j] = 1;
            }
        }
        __syncwarp();
    }
    for (int t = lane; t < nl; t += 32) {
        if (supp[t]) {
            int p = posArr[t];
            atomicOr(&g_remv[b * 64 + (p >> 6)], 1ull << (p & 63));
        }
    }
}

// ---------------- k7: post-NMS top-300 + float output ----------------
__device__ __forceinline__ int kth_bit(unsigned long long x, int k) {
    for (int b = 0; b < 64; b++) {
        if ((x >> b) & 1ull) { if (k == 0) return b; k--; }
    }
    return 63;
}

__global__ void k7_final(float* __restrict__ out, int out_size) {
    int b = blockIdx.x, t = threadIdx.x;
    __shared__ unsigned long long kw[64], nw[64];
    __shared__ int kpre[65], npre[65];
    if (t < 64) {
        unsigned long long r = g_remv[b * 64 + t];
        kw[t] = ~r;                         // keep = valid & not suppressed
        unsigned long long nk = r;          // not-kept, minus padding bit 4095
        if (t == 63) nk &= ~(1ull << 63);
        nw[t] = nk;
    }
    __syncthreads();
    if (t == 0) {
        int rk = 0, rn = 0;
        for (int w = 0; w < 64; w++) {
            kpre[w] = rk; rk += __popcll(kw[w]);
            npre[w] = rn; rn += __popcll(nw[w]);
        }
        kpre[64] = rk; npre[64] = rn;
    }
    __syncthreads();
    if (t >= POSTK) return;
    int kc = kpre[64];
    int p, sc;
    if (t < kc) {                            // kept, in slot (score) order
        int w = 0; while (kpre[w + 1] <= t) w++;
        p = w * 64 + kth_bit(kw[w], t - kpre[w]);
        sc = g_sortScore[b * KPAD + p];
    } else {                                 // NEG fillers: not-kept, ascending slot
        int q = t - kc;
        int w = 0; while (npre[w + 1] <= q) w++;
        p = w * 64 + kth_bit(nw[w], q - npre[w]);
        sc = NEGV;
    }
    float4 bxv = g_boxes[b * KPAD + p];
    int lab = g_sortLabel[b * KPAD + p];
    int base = (b * POSTK + t) * 4;
    out[base + 0] = (float)__float2int_rn(__fmul_rn(bxv.x, 4.f));  // half-even
    out[base + 1] = (float)__float2int_rn(__fmul_rn(bxv.y, 4.f));
    out[base + 2] = (float)__float2int_rn(__fmul_rn(bxv.z, 4.f));
    out[base + 3] = (float)__float2int_rn(__fmul_rn(bxv.w, 4.f));
    int so = BB * POSTK * 4 + b * POSTK + t;
    if (so < out_size) out[so] = (float)sc;
    int lo = BB * POSTK * 5 + b * POSTK + t;
    if (lo < out_size) out[lo] = (float)lab;
}

// ---------------- launch ----------------
extern "C" void kernel_launch(void* const* d_in, const int* in_sizes, int n_in,
                              void* d_out, int out_size) {
    const int*   data   = nullptr;
    const float* anchor = nullptr;
    const int*   exptab = nullptr;
    for (int i = 0; i < n_in; i++) {
        if (in_sizes[i] == SZ_DATA)        data   = (const int*)d_in[i];
        else if (in_sizes[i] == SZ_ANCHOR) anchor = (const float*)d_in[i];
        else if (in_sizes[i] == SZ_EXPTAB) exptab = (const int*)d_in[i];
    }
    if (!data   && n_in > 0) data   = (const int*)d_in[0];
    if (!anchor && n_in > 1) anchor = (const float*)d_in[1];
    if (!exptab && n_in > 2) exptab = (const int*)d_in[2];
    float* out = (float*)d_out;

    int fillN = out_size;
    if (fillN > 16384) fillN = 16384;
    if (fillN > 0) k0_fill<<<(fillN + 255) / 256, 256>>>(out, fillN);

    k1_score<<<dim3(NCHUNK, BB), 256>>>(data);       // 256 thr * 4 cands = 1024 chunk
    k2_base<<<BB, BINS>>>();
    k3_scatter<<<dim3(NCHUNK / 4, BB), 128>>>();
    k4_decode<<<(BB * KPAD) / 256, 256>>>(data, anchor, exptab);
    k5_part<<<BB, 32>>>();
    k6_nms<<<dim3(NLAB, BB), 32>>>();
    k7_final<<<BB, 512>>>(out, out_size);
}

// round 15
// speedup vs baseline: 2.7339x; 1.6692x over previous
#include <cuda_runtime.h>
#include <stdint.h>

// ---------------- problem constants ----------------
#define BB 4
#define AA 6
#define CC 80
#define HH 128
#define WW 128
#define HWP (HH*WW)            // 16384
#define NN (AA*HWP)            // 98304
#define NCHAN (AA*(4+CC))      // 504
#define KPRE 4095
#define KPAD 4096
#define POSTK 300
#define NEGV (-(1<<30))
#define BINS 128
#define CHUNK 1024
#define NCHUNK (NN/CHUNK)      // 96
#define NLAB 80
#define CAPB 1024
#define ESC (1.0f/16.0f)       // exp_shift == 4 analytically
#define OUT_ELEMS (BB*POSTK*6) // 7200

// expected input element counts (order-independent identification)
#define SZ_DATA   (BB*NCHAN*HWP)   // 33030144
#define SZ_ANCHOR (AA*4*HWP)       // 393216
#define SZ_EXPTAB 256

// ---------------- scratch (static device memory; no allocation) ----------------
__device__ int8_t  g_score[BB*NN];
__device__ uint8_t g_label[BB*NN];
__device__ int     g_hist[BB*BINS*NCHUNK];
__device__ int     g_base[BB*BINS*NCHUNK];
__device__ int     g_sortIdx[BB*KPAD];
__device__ int     g_sortScore[BB*KPAD];
__device__ int     g_sortLabel[BB*KPAD];
__device__ float4  g_boxes[BB*KPAD];
__device__ unsigned long long g_remv[BB*64];   // suppression bits ONLY (zeroed in k2)

// ---------------- k0: zero-fill d_out ----------------
__global__ void k0_fill(float* __restrict__ out, int n) {
    int i = blockIdx.x * blockDim.x + threadIdx.x;
    if (i < n) out[i] = 0.0f;
}

// ---------------- k1: class max/argmax (int4-vectorized) + per-chunk histogram -
__global__ void k1_score(const int* __restrict__ data) {
    int chunk = blockIdx.x, b = blockIdx.y, t = threadIdx.x;
    int n0 = chunk * CHUNK + t * 4;
    int a = n0 >> 14, hw = n0 & (HWP - 1);
    const int* p = data + (((size_t)(b * NCHAN + a * (4 + CC) + 4)) << 14) + hw;
    int4 v = *(const int4*)p;
    int b0 = v.x, b1 = v.y, b2 = v.z, b3 = v.w;
    int l0 = 0, l1 = 0, l2 = 0, l3 = 0;
#pragma unroll 8
    for (int c = 1; c < CC; c++) {
        int4 w = *(const int4*)(p + ((size_t)c << 14));
        if (w.x > b0) { b0 = w.x; l0 = c; }
        if (w.y > b1) { b1 = w.y; l1 = c; }
        if (w.z > b2) { b2 = w.z; l2 = c; }
        if (w.w > b3) { b3 = w.w; l3 = c; }
    }
    char4 sc4; sc4.x = (char)b0; sc4.y = (char)b1; sc4.z = (char)b2; sc4.w = (char)b3;
    *(char4*)&g_score[b * NN + n0] = sc4;
    uchar4 lb4; lb4.x = (unsigned char)l0; lb4.y = (unsigned char)l1;
    lb4.z = (unsigned char)l2; lb4.w = (unsigned char)l3;
    *(uchar4*)&g_label[b * NN + n0] = lb4;

    __shared__ int sh[BINS];
    if (t < BINS) sh[t] = 0;
    __syncthreads();
    atomicAdd(&sh[(b0 >= 1) ? (127 - b0) : 127], 1);
    atomicAdd(&sh[(b1 >= 1) ? (127 - b1) : 127], 1);
    atomicAdd(&sh[(b2 >= 1) ? (127 - b2) : 127], 1);
    atomicAdd(&sh[(b3 >= 1) ? (127 - b3) : 127], 1);
    __syncthreads();
    if (t < BINS) g_hist[(b * BINS + t) * NCHUNK + chunk] = sh[t];
}

// ---------------- k2: global exclusive bases + remv zero + pad-slot stamp ------
__global__ void k2_base() {
    int b = blockIdx.x, bin = threadIdx.x;
    if (bin < 64) g_remv[b * 64 + bin] = 0ull;          // suppression bits reset
    if (bin == 0) g_sortScore[b * KPAD + KPRE] = NEGV;   // pad slot never valid
    const int* row = g_hist + (b * BINS + bin) * NCHUNK;
    int sum = 0;
#pragma unroll 8
    for (int c = 0; c < NCHUNK; c++) sum += row[c];
    __shared__ int tot[BINS];
    __shared__ int bb[BINS];
    tot[bin] = sum;
    __syncthreads();
    if (bin == 0) { int r = 0; for (int i = 0; i < BINS; i++) { bb[i] = r; r += tot[i]; } }
    __syncthreads();
    int run = bb[bin];
    int* orow = g_base + (b * BINS + bin) * NCHUNK;
#pragma unroll 8
    for (int c = 0; c < NCHUNK; c++) { int tc = row[c]; orow[c] = run; run += tc; }
}

// ---------------- k3: warp-parallel stable scatter (smem-resident bases) -------
__global__ void k3_scatter() {
    int b = blockIdx.y;
    int wid = threadIdx.x >> 5, lane = threadIdx.x & 31;
    int chunk = blockIdx.x * 4 + wid;
    __shared__ int cnt[4][BINS];
    __shared__ int sbase[4][BINS];
    for (int i = lane; i < BINS; i += 32) {
        cnt[wid][i] = 0;
        sbase[wid][i] = g_base[(b * BINS + i) * NCHUNK + chunk];  // one-time preload
    }
    __syncwarp();
    for (int g = 0; g < CHUNK / 32; g++) {
        int n = chunk * CHUNK + g * 32 + lane;
        int s = g_score[b * NN + n];
        int lab = g_label[b * NN + n];
        int bin = (s >= 1) ? (127 - s) : 127;
        unsigned m = __match_any_sync(0xffffffffu, bin);
        int prior = cnt[wid][bin];
        __syncwarp();
        if (lane == __ffs(m) - 1) cnt[wid][bin] = prior + __popc(m);
        __syncwarp();
        int ltr = __popc(m & ((1u << lane) - 1u));
        int pos = sbase[wid][bin] + prior + ltr;
        if (pos < KPRE) {
            g_sortIdx[b * KPAD + pos] = n;
            g_sortScore[b * KPAD + pos] = (s >= 1) ? s : NEGV;
            g_sortLabel[b * KPAD + pos] = lab;
        }
    }
}

// ---------------- k4: decode boxes (fp32, no-FMA) ----------------
__global__ void k4_decode(const int* __restrict__ data, const float* __restrict__ anchor,
                          const int* __restrict__ exptab) {
    int t = blockIdx.x * blockDim.x + threadIdx.x;
    int b = t >> 12, slot = t & (KPAD - 1);
    if (b >= BB || slot >= KPRE) return;
    int n = g_sortIdx[b * KPAD + slot];
    n = min(max(n, 0), NN - 1);
    int a = n >> 14, hw = n & (HWP - 1);
    size_t db = (((size_t)(b * NCHAN + a * (4 + CC))) << 14) + hw;
    int d0 = data[db], d1 = data[db + HWP], d2 = data[db + 2 * HWP], d3 = data[db + 3 * HWP];
    size_t ab = (((size_t)(a * 4)) << 14) + hw;
    float x1 = anchor[ab], y1 = anchor[ab + HWP], x2 = anchor[ab + 2 * HWP], y2 = anchor[ab + 3 * HWP];
    float aw = __fsub_rn(x2, x1), ah = __fsub_rn(y2, y1);
    float acx = __fmul_rn(__fadd_rn(x1, x2), 0.5f);
    float acy = __fmul_rn(__fadd_rn(y1, y2), 0.5f);
    float dx = __fmul_rn((float)d0, 0.0625f);
    float dy = __fmul_rn((float)d1, 0.0625f);
    int i2 = min(max(d2, -128), 127) + 128;
    int i3 = min(max(d3, -128), 127) + 128;
    float ew = __fmul_rn((float)exptab[i2], ESC);
    float eh = __fmul_rn((float)exptab[i3], ESC);
    float pcx = __fadd_rn(acx, __fmul_rn(dx, aw));
    float pcy = __fadd_rn(acy, __fmul_rn(dy, ah));
    float pw = __fmul_rn(aw, ew), ph = __fmul_rn(ah, eh);
    float pwh = __fmul_rn(pw, 0.5f), phh = __fmul_rn(ph, 0.5f);
    float bx1 = fminf(fmaxf(__fsub_rn(pcx, pwh), 0.f), 1024.f);
    float by1 = fminf(fmaxf(__fsub_rn(pcy, phh), 0.f), 1024.f);
    float bx2 = fminf(fmaxf(__fadd_rn(pcx, pwh), 0.f), 1024.f);
    float by2 = fminf(fmaxf(__fadd_rn(pcy, phh), 0.f), 1024.f);
    g_boxes[b * KPAD + slot] = make_float4(bx1, by1, bx2, by2);
}

// ---------------- k6: fused compaction + per-(batch,label) greedy NMS ----------
// Each block builds its own stable label group via ballot compaction (ascending
// slot order => stable), then runs exact greedy NMS within the group.
__global__ void k6_nms() {
    int b = blockIdx.y, lab = blockIdx.x, lane = threadIdx.x;
    __shared__ int posArr[KPAD];
    __shared__ float4 bx[CAPB];
    __shared__ unsigned char supp[KPAD];

    int myCnt = 0;
#pragma unroll 4
    for (int g = 0; g < KPAD / 32; g++) {
        int idx = g * 32 + lane;
        int s = g_sortScore[b * KPAD + idx];
        int lb = g_sortLabel[b * KPAD + idx];
        bool take = (idx < KPRE) && (s != NEGV) && (lb == lab);
        unsigned m = __ballot_sync(0xffffffffu, take);
        if (take) posArr[myCnt + __popc(m & ((1u << lane) - 1u))] = idx;
        myCnt += __popc(m);
    }
    int nl = myCnt;                      // warp-uniform (ballot-derived)
    if (nl <= 1) return;
    __syncwarp();
    for (int t = lane; t < nl; t += 32) {
        supp[t] = 0;
        if (t < CAPB) bx[t] = g_boxes[b * KPAD + posArr[t]];
    }
    __syncwarp();
    for (int i = 0; i < nl - 1; i++) {
        if (!supp[i]) {
            float4 bi = (i < CAPB) ? bx[i] : g_boxes[b * KPAD + posArr[i]];
            float ai = __fmul_rn(fmaxf(__fsub_rn(bi.z, bi.x), 0.f),
                                 fmaxf(__fsub_rn(bi.w, bi.y), 0.f));
            for (int j = i + 1 + lane; j < nl; j += 32) {
                if (supp[j]) continue;
                float4 bj = (j < CAPB) ? bx[j] : g_boxes[b * KPAD + posArr[j]];
                float aj = __fmul_rn(fmaxf(__fsub_rn(bj.z, bj.x), 0.f),
                                     fmaxf(__fsub_rn(bj.w, bj.y), 0.f));
                float ltx = fmaxf(bi.x, bj.x), lty = fmaxf(bi.y, bj.y);
                float rbx = fminf(bi.z, bj.z), rby = fminf(bi.w, bj.w);
                float wx = fmaxf(__fsub_rn(rbx, ltx), 0.f);
                float wy = fmaxf(__fsub_rn(rby, lty), 0.f);
                float inter = __fmul_rn(wx, wy);
                float uni = __fsub_rn(__fadd_rn(ai, aj), inter);
                float den = fmaxf(uni, 1e-6f);
                float iou = __fdiv_rn(inter, den);
                if (iou > 0.5f) supp[j] = 1;
            }
        }
        __syncwarp();
    }
    for (int t = lane; t < nl; t += 32) {
        if (supp[t]) {
            int p = posArr[t];
            atomicOr(&g_remv[b * 64 + (p >> 6)], 1ull << (p & 63));
        }
    }
}

// ---------------- k7: validity ballots + post-NMS top-300 + float output -------
__device__ __forceinline__ int kth_bit(unsigned long long x, int k) {
    for (int b = 0; b < 64; b++) {
        if ((x >> b) & 1ull) { if (k == 0) return b; k--; }
    }
    return 63;
}

__global__ void k7_final(float* __restrict__ out, int out_size) {
    int b = blockIdx.x, t = threadIdx.x;           // 512 threads = 16 warps
    int warp = t >> 5, lane = t & 31;
    __shared__ unsigned long long kw[64], nw[64];
    __shared__ int kpre[65], npre[65];
    for (int w = warp * 4; w < warp * 4 + 4; w++) {  // each warp builds 4 words
        int i0 = w * 64 + lane, i1 = i0 + 32;
        bool v0 = (i0 < KPRE) && (g_sortScore[b * KPAD + i0] != NEGV);
        bool v1 = (i1 < KPRE) && (g_sortScore[b * KPAD + i1] != NEGV);
        unsigned lo = __ballot_sync(0xffffffffu, v0);
        unsigned hi = __ballot_sync(0xffffffffu, v1);
        if (lane == 0) {
            unsigned long long valid = (unsigned long long)lo | ((unsigned long long)hi << 32);
            unsigned long long keep = valid & ~g_remv[b * 64 + w];
            kw[w] = keep;
            unsigned long long nk = ~keep;
            if (w == 63) nk &= ~(1ull << 63);       // exclude pad slot from fillers
            nw[w] = nk;
        }
    }
    __syncthreads();
    if (t == 0) {
        int rk = 0, rn = 0;
        for (int w = 0; w < 64; w++) {
            kpre[w] = rk; rk += __popcll(kw[w]);
            npre[w] = rn; rn += __popcll(nw[w]);
        }
        kpre[64] = rk; npre[64] = rn;
    }
    __syncthreads();
    if (t >= POSTK) return;
    int kc = kpre[64];
    int p, sc;
    if (t < kc) {                            // kept, in slot (score) order
        int w = 0; while (kpre[w + 1] <= t) w++;
        p = w * 64 + kth_bit(kw[w], t - kpre[w]);
        sc = g_sortScore[b * KPAD + p];
    } else {                                 // NEG fillers: not-kept, ascending slot
        int q = t - kc;
        int w = 0; while (npre[w + 1] <= q) w++;
        p = w * 64 + kth_bit(nw[w], q - npre[w]);
        sc = NEGV;
    }
    float4 bxv = g_boxes[b * KPAD + p];
    int lab = g_sortLabel[b * KPAD + p];
    int base = (b * POSTK + t) * 4;
    out[base + 0] = (float)__float2int_rn(__fmul_rn(bxv.x, 4.f));  // half-even
    out[base + 1] = (float)__float2int_rn(__fmul_rn(bxv.y, 4.f));
    out[base + 2] = (float)__float2int_rn(__fmul_rn(bxv.z, 4.f));
    out[base + 3] = (float)__float2int_rn(__fmul_rn(bxv.w, 4.f));
    int so = BB * POSTK * 4 + b * POSTK + t;
    if (so < out_size) out[so] = (float)sc;
    int lo = BB * POSTK * 5 + b * POSTK + t;
    if (lo < out_size) out[lo] = (float)lab;
}

// ---------------- launch ----------------
extern "C" void kernel_launch(void* const* d_in, const int* in_sizes, int n_in,
                              void* d_out, int out_size) {
    const int*   data   = nullptr;
    const float* anchor = nullptr;
    const int*   exptab = nullptr;
    for (int i = 0; i < n_in; i++) {
        if (in_sizes[i] == SZ_DATA)        data   = (const int*)d_in[i];
        else if (in_sizes[i] == SZ_ANCHOR) anchor = (const float*)d_in[i];
        else if (in_sizes[i] == SZ_EXPTAB) exptab = (const int*)d_in[i];
    }
    if (!data   && n_in > 0) data   = (const int*)d_in[0];
    if (!anchor && n_in > 1) anchor = (const float*)d_in[1];
    if (!exptab && n_in > 2) exptab = (const int*)d_in[2];
    float* out = (float*)d_out;

    int fillN = out_size;
    if (fillN > 16384) fillN = 16384;
    if (fillN > 0) k0_fill<<<(fillN + 255) / 256, 256>>>(out, fillN);

    k1_score<<<dim3(NCHUNK, BB), 256>>>(data);
    k2_base<<<BB, BINS>>>();
    k3_scatter<<<dim3(NCHUNK / 4, BB), 128>>>();
    k4_decode<<<(BB * KPAD) / 256, 256>>>(data, anchor, exptab);
    k6_nms<<<dim3(NLAB, BB), 32>>>();
    k7_final<<<BB, 512>>>(out, out_size);
}

// round 17
// speedup vs baseline: 2.7480x; 1.0051x over previous
#include <cuda_runtime.h>
#include <stdint.h>

// ---------------- problem constants ----------------
#define BB 4
#define AA 6
#define CC 80
#define HH 128
#define WW 128
#define HWP (HH*WW)            // 16384
#define NN (AA*HWP)            // 98304
#define NCHAN (AA*(4+CC))      // 504
#define KPRE 4095
#define KPAD 4096
#define POSTK 300
#define NEGV (-(1<<30))
#define BINS 128
#define SUBC 256               // counting-sort granularity
#define NCHUNK (NN/SUBC)       // 384 subchunks per batch
#define NLAB 80
#define CAPB 1024
#define ESC (1.0f/16.0f)       // exp_shift == 4 analytically
#define OUT_ELEMS (BB*POSTK*6) // 7200

// expected input element counts (order-independent identification)
#define SZ_DATA   (BB*NCHAN*HWP)   // 33030144
#define SZ_ANCHOR (AA*4*HWP)       // 393216
#define SZ_EXPTAB 256

// ---------------- scratch (static device memory; no allocation) ----------------
__device__ int8_t  g_score[BB*NN];
__device__ uint8_t g_label[BB*NN];
__device__ int     g_hist[BB*NCHUNK*BINS];   // subchunk-major: [b][sc][bin]
__device__ int     g_base[BB*NCHUNK*BINS];   // subchunk-major: [b][sc][bin]
__device__ int     g_sortScore[BB*KPAD];
__device__ int     g_sortLabel[BB*KPAD];
__device__ float4  g_boxes[BB*KPAD];
__device__ unsigned long long g_remv[BB*64]; // suppression bits ONLY (zeroed in k2)

// ---------------- k0: zero-fill tail of d_out (only if out_size > 7200) --------
__global__ void k0_fill(float* __restrict__ out, int n) {
    int i = blockIdx.x * blockDim.x + threadIdx.x;
    if (i < n) out[i] = 0.0f;
}

// ---------------- k1: class max/argmax (int4, streaming) + per-subchunk hist ---
// Block: 256 threads covering 1024 candidates = 4 subchunks of 256.
// bin = 127 - s for s in [1,127] (descending score), bin 127 = below-threshold.
__global__ void k1_score(const int* __restrict__ data) {
    int chunk = blockIdx.x, b = blockIdx.y, t = threadIdx.x;
    int n0 = chunk * 1024 + t * 4;
    int sub = t >> 6;                        // subchunk within block (0..3)
    int a = n0 >> 14, hw = n0 & (HWP - 1);
    const int4* p = (const int4*)(data + (((size_t)(b * NCHAN + a * (4 + CC) + 4)) << 14) + hw);
    int4 v = __ldcs(p);
    int b0 = v.x, b1 = v.y, b2 = v.z, b3 = v.w;
    int l0 = 0, l1 = 0, l2 = 0, l3 = 0;
#pragma unroll 8
    for (int c = 1; c < CC; c++) {
        int4 w = __ldcs((const int4*)((const int*)p + ((size_t)c << 14)));
        if (w.x > b0) { b0 = w.x; l0 = c; }
        if (w.y > b1) { b1 = w.y; l1 = c; }
        if (w.z > b2) { b2 = w.z; l2 = c; }
        if (w.w > b3) { b3 = w.w; l3 = c; }
    }
    char4 sc4; sc4.x = (char)b0; sc4.y = (char)b1; sc4.z = (char)b2; sc4.w = (char)b3;
    *(char4*)&g_score[b * NN + n0] = sc4;
    uchar4 lb4; lb4.x = (unsigned char)l0; lb4.y = (unsigned char)l1;
    lb4.z = (unsigned char)l2; lb4.w = (unsigned char)l3;
    *(uchar4*)&g_label[b * NN + n0] = lb4;

    __shared__ int sh[4][BINS];
    for (int i = t; i < 4 * BINS; i += 256) ((int*)sh)[i] = 0;
    __syncthreads();
    atomicAdd(&sh[sub][(b0 >= 1) ? (127 - b0) : 127], 1);
    atomicAdd(&sh[sub][(b1 >= 1) ? (127 - b1) : 127], 1);
    atomicAdd(&sh[sub][(b2 >= 1) ? (127 - b2) : 127], 1);
    atomicAdd(&sh[sub][(b3 >= 1) ? (127 - b3) : 127], 1);
    __syncthreads();
    // write 4 subchunk histograms, coalesced
    int base = (b * NCHUNK + chunk * 4) * BINS;
    for (int i = t; i < 4 * BINS; i += 256) g_hist[base + i] = ((int*)sh)[i];
}

// ---------------- k2: exclusive bases (bin-major, subchunk-minor) + remv zero --
__global__ void k2_base() {
    int b = blockIdx.x, bin = threadIdx.x;
    if (bin < 64) g_remv[b * 64 + bin] = 0ull;
    if (bin == 0) g_sortScore[b * KPAD + KPRE] = NEGV;    // pad slot never valid
    int sum = 0;
#pragma unroll 8
    for (int c = 0; c < NCHUNK; c++) sum += g_hist[(b * NCHUNK + c) * BINS + bin];
    __shared__ int tot[BINS];
    __shared__ int bb[BINS];
    tot[bin] = sum;
    __syncthreads();
    if (bin == 0) { int r = 0; for (int i = 0; i < BINS; i++) { bb[i] = r; r += tot[i]; } }
    __syncthreads();
    int run = bb[bin];
#pragma unroll 8
    for (int c = 0; c < NCHUNK; c++) {
        int idx = (b * NCHUNK + c) * BINS + bin;
        int tc = g_hist[idx];
        g_base[idx] = run; run += tc;
    }
}

// ---------------- k3: stable scatter + fused box decode ------------------------
// One warp per 256-subchunk (8 groups); groups+lanes ascending => stable.
__global__ void k3_scatter(const int* __restrict__ data, const float* __restrict__ anchor,
                           const int* __restrict__ exptab) {
    int b = blockIdx.y;
    int wid = threadIdx.x >> 5, lane = threadIdx.x & 31;
    int sc = blockIdx.x * 4 + wid;           // subchunk id
    __shared__ int cnt[4][BINS];
    __shared__ int sbase[4][BINS];
    for (int i = lane; i < BINS; i += 32) {
        cnt[wid][i] = 0;
        sbase[wid][i] = __ldg(&g_base[(b * NCHUNK + sc) * BINS + i]);  // coalesced preload
    }
    __syncwarp();
#pragma unroll
    for (int g = 0; g < SUBC / 32; g++) {
        int n = sc * SUBC + g * 32 + lane;
        int s = g_score[b * NN + n];
        int lab = g_label[b * NN + n];
        int bin = (s >= 1) ? (127 - s) : 127;
        unsigned m = __match_any_sync(0xffffffffu, bin);
        int prior = cnt[wid][bin];
        __syncwarp();
        if (lane == __ffs(m) - 1) cnt[wid][bin] = prior + __popc(m);
        __syncwarp();
        int pos = sbase[wid][bin] + prior + __popc(m & ((1u << lane) - 1u));
        if (pos < KPRE) {
            g_sortScore[b * KPAD + pos] = (s >= 1) ? s : NEGV;
            g_sortLabel[b * KPAD + pos] = lab;
            // ---- fused decode (fp32, no-FMA to match XLA fp32 graph) ----
            int a = n >> 14, hw = n & (HWP - 1);
            size_t db = (((size_t)(b * NCHAN + a * (4 + CC))) << 14) + hw;
            int d0 = data[db], d1 = data[db + HWP], d2 = data[db + 2 * HWP], d3 = data[db + 3 * HWP];
            size_t ab = (((size_t)(a * 4)) << 14) + hw;
            float x1 = anchor[ab], y1 = anchor[ab + HWP];
            float x2 = anchor[ab + 2 * HWP], y2 = anchor[ab + 3 * HWP];
            float aw = __fsub_rn(x2, x1), ah = __fsub_rn(y2, y1);
            float acx = __fmul_rn(__fadd_rn(x1, x2), 0.5f);
            float acy = __fmul_rn(__fadd_rn(y1, y2), 0.5f);
            float dx = __fmul_rn((float)d0, 0.0625f);
            float dy = __fmul_rn((float)d1, 0.0625f);
            int i2 = min(max(d2, -128), 127) + 128;
            int i3 = min(max(d3, -128), 127) + 128;
            float ew = __fmul_rn((float)__ldg(&exptab[i2]), ESC);
            float eh = __fmul_rn((float)__ldg(&exptab[i3]), ESC);
            float pcx = __fadd_rn(acx, __fmul_rn(dx, aw));
            float pcy = __fadd_rn(acy, __fmul_rn(dy, ah));
            float pw = __fmul_rn(aw, ew), ph = __fmul_rn(ah, eh);
            float pwh = __fmul_rn(pw, 0.5f), phh = __fmul_rn(ph, 0.5f);
            float bx1 = fminf(fmaxf(__fsub_rn(pcx, pwh), 0.f), 1024.f);
            float by1 = fminf(fmaxf(__fsub_rn(pcy, phh), 0.f), 1024.f);
            float bx2 = fminf(fmaxf(__fadd_rn(pcx, pwh), 0.f), 1024.f);
            float by2 = fminf(fmaxf(__fadd_rn(pcy, phh), 0.f), 1024.f);
            g_boxes[b * KPAD + pos] = make_float4(bx1, by1, bx2, by2);
        }
    }
}

// ---------------- k6: fused compaction + per-(batch,label) greedy NMS ----------
__global__ void k6_nms() {
    int b = blockIdx.y, lab = blockIdx.x, lane = threadIdx.x;
    __shared__ int posArr[KPAD];
    __shared__ float4 bx[CAPB];
    __shared__ unsigned char supp[KPAD];

    int myCnt = 0;
#pragma unroll 4
    for (int g = 0; g < KPAD / 32; g++) {
        int idx = g * 32 + lane;
        int s = g_sortScore[b * KPAD + idx];
        int lb = g_sortLabel[b * KPAD + idx];
        bool take = (idx < KPRE) && (s != NEGV) && (lb == lab);
        unsigned m = __ballot_sync(0xffffffffu, take);
        if (take) posArr[myCnt + __popc(m & ((1u << lane) - 1u))] = idx;
        myCnt += __popc(m);
    }
    int nl = myCnt;                      // warp-uniform
    if (nl <= 1) return;
    __syncwarp();
    for (int t = lane; t < nl; t += 32) {
        supp[t] = 0;
        if (t < CAPB) bx[t] = g_boxes[b * KPAD + posArr[t]];
    }
    __syncwarp();
    for (int i = 0; i < nl - 1; i++) {
        if (!supp[i]) {
            float4 bi = (i < CAPB) ? bx[i] : g_boxes[b * KPAD + posArr[i]];
            float ai = __fmul_rn(fmaxf(__fsub_rn(bi.z, bi.x), 0.f),
                                 fmaxf(__fsub_rn(bi.w, bi.y), 0.f));
            for (int j = i + 1 + lane; j < nl; j += 32) {
                if (supp[j]) continue;
                float4 bj = (j < CAPB) ? bx[j] : g_boxes[b * KPAD + posArr[j]];
                float aj = __fmul_rn(fmaxf(__fsub_rn(bj.z, bj.x), 0.f),
                                     fmaxf(__fsub_rn(bj.w, bj.y), 0.f));
                float ltx = fmaxf(bi.x, bj.x), lty = fmaxf(bi.y, bj.y);
                float rbx = fminf(bi.z, bj.z), rby = fminf(bi.w, bj.w);
                float wx = fmaxf(__fsub_rn(rbx, ltx), 0.f);
                float wy = fmaxf(__fsub_rn(rby, lty), 0.f);
                float inter = __fmul_rn(wx, wy);
                float uni = __fsub_rn(__fadd_rn(ai, aj), inter);
                float den = fmaxf(uni, 1e-6f);
                float iou = __fdiv_rn(inter, den);
                if (iou > 0.5f) supp[j] = 1;
            }
        }
        __syncwarp();
    }
    for (int t = lane; t < nl; t += 32) {
        if (supp[t]) {
            int p = posArr[t];
            atomicOr(&g_remv[b * 64 + (p >> 6)], 1ull << (p & 63));
        }
    }
}

// ---------------- k7: validity ballots + post-NMS top-300 + float output -------
__device__ __forceinline__ int kth_bit(unsigned long long x, int k) {
    for (int b = 0; b < 64; b++) {
        if ((x >> b) & 1ull) { if (k == 0) return b; k--; }
    }
    return 63;
}

__global__ void k7_final(float* __restrict__ out, int out_size) {
    int b = blockIdx.x, t = threadIdx.x;           // 512 threads = 16 warps
    int warp = t >> 5, lane = t & 31;
    __shared__ unsigned long long kw[64], nw[64];
    __shared__ int kpre[65], npre[65];
    for (int w = warp * 4; w < warp * 4 + 4; w++) {
        int i0 = w * 64 + lane, i1 = i0 + 32;
        bool v0 = (i0 < KPRE) && (g_sortScore[b * KPAD + i0] != NEGV);
        bool v1 = (i1 < KPRE) && (g_sortScore[b * KPAD + i1] != NEGV);
        unsigned lo = __ballot_sync(0xffffffffu, v0);
        unsigned hi = __ballot_sync(0xffffffffu, v1);
        if (lane == 0) {
            unsigned long long valid = (unsigned long long)lo | ((unsigned long long)hi << 32);
            unsigned long long keep = valid & ~g_remv[b * 64 + w];
            kw[w] = keep;
            unsigned long long nk = ~keep;
            if (w == 63) nk &= ~(1ull << 63);       // exclude pad slot from fillers
            nw[w] = nk;
        }
    }
    __syncthreads();
    if (t == 0) {
        int rk = 0, rn = 0;
        for (int w = 0; w < 64; w++) {
            kpre[w] = rk; rk += __popcll(kw[w]);
            npre[w] = rn; rn += __popcll(nw[w]);
        }
        kpre[64] = rk; npre[64] = rn;
    }
    __syncthreads();
    if (t >= POSTK) return;
    int kc = kpre[64];
    int p, sc;
    if (t < kc) {                            // kept, in slot (score) order
        int w = 0; while (kpre[w + 1] <= t) w++;
        p = w * 64 + kth_bit(kw[w], t - kpre[w]);
        sc = g_sortScore[b * KPAD + p];
    } else {                                 // NEG fillers: not-kept, ascending slot
        int q = t - kc;
        int w = 0; while (npre[w + 1] <= q) w++;
        p = w * 64 + kth_bit(nw[w], q - npre[w]);
        sc = NEGV;
    }
    float4 bxv = g_boxes[b * KPAD + p];
    int lab = g_sortLabel[b * KPAD + p];
    int base = (b * POSTK + t) * 4;
    out[base + 0] = (float)__float2int_rn(__fmul_rn(bxv.x, 4.f));  // half-even
    out[base + 1] = (float)__float2int_rn(__fmul_rn(bxv.y, 4.f));
    out[base + 2] = (float)__float2int_rn(__fmul_rn(bxv.z, 4.f));
    out[base + 3] = (float)__float2int_rn(__fmul_rn(bxv.w, 4.f));
    int so = BB * POSTK * 4 + b * POSTK + t;
    if (so < out_size) out[so] = (float)sc;
    int lo = BB * POSTK * 5 + b * POSTK + t;
    if (lo < out_size) out[lo] = (float)lab;
}

// ---------------- launch ----------------
extern "C" void kernel_launch(void* const* d_in, const int* in_sizes, int n_in,
                              void* d_out, int out_size) {
    const int*   data   = nullptr;
    const float* anchor = nullptr;
    const int*   exptab = nullptr;
    for (int i = 0; i < n_in; i++) {
        if (in_sizes[i] == SZ_DATA)        data   = (const int*)d_in[i];
        else if (in_sizes[i] == SZ_ANCHOR) anchor = (const float*)d_in[i];
        else if (in_sizes[i] == SZ_EXPTAB) exptab = (const int*)d_in[i];
    }
    if (!data   && n_in > 0) data   = (const int*)d_in[0];
    if (!anchor && n_in > 1) anchor = (const float*)d_in[1];
    if (!exptab && n_in > 2) exptab = (const int*)d_in[2];
    float* out = (float*)d_out;

    // k7 writes all 7200 elements; only pre-fill if the buffer is larger.
    if (out_size > OUT_ELEMS) {
        int fillN = out_size;
        if (fillN > 65536) fillN = 65536;
        k0_fill<<<(fillN + 255) / 256, 256>>>(out, fillN);
    }

    k1_score<<<dim3(NN / 1024, BB), 256>>>(data);     // 96 x 4 blocks
    k2_base<<<BB, BINS>>>();
    k3_scatter<<<dim3(NCHUNK / 4, BB), 128>>>(data, anchor, exptab);  // 96 x 4 blocks
    k6_nms<<<dim3(NLAB, BB), 32>>>();
    k7_final<<<BB, 512>>>(out, out_size);
}